// round 14
// baseline (speedup 1.0000x reference)
#include <cuda_runtime.h>
#include <cuda_bf16.h>

// ROI-Align (Mask R-CNN multi-level crop_and_resize), POOL=7, C=256, N=1000.
// R9: level/channel-major. k2 block = (channel-group of 8, level, chunk):
// per-sample bilinear params loaded once per 8 channels; 32 independent gathers
// per param load. Prep fused into kZ (zero) + kAB (level+compact+params).

#define NBOX  1000
#define POOLP 49
#define CCH   256
#define MAXS  (NBOX * POOLP)
#define CPT   8                  // channels per thread in hot kernel
#define NCG   (CCH / CPT)        // 32 channel groups
#define CHUNKS 8
#define BOXPB 125                // boxes per kAB block (8 blocks)

__device__ int    g_count[4];
__device__ int4   g_off[4][MAXS];    // 4 clamped in-plane offsets
__device__ float4 g_wgt[4][MAXS];    // 4 bilinear weights (mask folded in)
__device__ int    g_ob [4][MAXS];    // n*12544 + pos (output base sans channel)

// -- zero level counters ---------------------------------------------------
__global__ void kZ() {
    if (threadIdx.x < 4) g_count[threadIdx.x] = 0;
}

// -- fused: per-box level + compaction slot + per-sample params ------------
__global__ __launch_bounds__(256) void kAB(const float* __restrict__ boxes) {
    __shared__ int   s_l   [BOXPB];
    __shared__ int   s_slot[BOXPB];
    __shared__ float s_y1  [BOXPB];
    __shared__ float s_x1  [BOXPB];
    __shared__ float s_y2  [BOXPB];
    __shared__ float s_x2  [BOXPB];

    const int b0 = blockIdx.x * BOXPB;
    const int tid = threadIdx.x;

    if (tid < BOXPB) {
        const int n = b0 + tid;
        float y1 = boxes[n * 4 + 0];
        float x1 = boxes[n * 4 + 1];
        float y2 = boxes[n * 4 + 2];
        float x2 = boxes[n * 4 + 3];
        // roi_level = clip(round(4 + log2(sqrt(h*w)/0.21875)), 2, 5); round half-to-even.
        float lvl_f = 4.0f + log2f(sqrtf((y2 - y1) * (x2 - x1)) / 0.21875f);
        int lvl = (int)rintf(lvl_f);
        lvl = lvl < 2 ? 2 : (lvl > 5 ? 5 : lvl);
        int l = lvl - 2;
        s_l[tid]    = l;
        s_slot[tid] = atomicAdd(&g_count[l], 1);
        s_y1[tid] = y1; s_x1[tid] = x1; s_y2[tid] = y2; s_x2[tid] = x2;
    }
    __syncthreads();

    // 125 boxes * 49 samples = 6125 samples, 256 threads.
    for (int s = tid; s < BOXPB * POOLP; s += 256) {
        const int bi  = s / POOLP;
        const int pos = s - bi * POOLP;
        const int l    = s_l[bi];
        const int slot = s_slot[bi];
        const int py = pos / 7;
        const int px = pos - py * 7;

        const int H = 256 >> l;
        const int W = H;
        const float y1 = s_y1[bi], x1 = s_x1[bi], y2 = s_y2[bi], x2 = s_x2[bi];

        // Match jax f32 arithmetic (t = i / 6.0f as division).
        const float ty = (float)py / 6.0f;
        const float tx = (float)px / 6.0f;
        const float yy = (y1 + (y2 - y1) * ty) * (float)(H - 1);
        const float xx = (x1 + (x2 - x1) * tx) * (float)(W - 1);

        const float y0f = floorf(yy);
        const float x0f = floorf(xx);
        const float wy = yy - y0f;
        const float wx = xx - x0f;

        int iy0 = (int)y0f; iy0 = iy0 < 0 ? 0 : (iy0 > H - 1 ? H - 1 : iy0);
        int iy1 = (iy0 + 1 > H - 1) ? (H - 1) : (iy0 + 1);
        int ix0 = (int)x0f; ix0 = ix0 < 0 ? 0 : (ix0 > W - 1 ? W - 1 : ix0);
        int ix1 = (ix0 + 1 > W - 1) ? (W - 1) : (ix0 + 1);

        const bool inb = (yy >= 0.0f) && (yy <= (float)(H - 1)) &&
                         (xx >= 0.0f) && (xx <= (float)(W - 1));
        const float m = inb ? 1.0f : 0.0f;

        int4 o;
        o.x = iy0 * W + ix0;
        o.y = iy0 * W + ix1;
        o.z = iy1 * W + ix0;
        o.w = iy1 * W + ix1;
        float4 w;
        w.x = m * (1.0f - wy) * (1.0f - wx);
        w.y = m * (1.0f - wy) * wx;
        w.z = m * wy * (1.0f - wx);
        w.w = m * wy * wx;

        const int j = slot * POOLP + pos;
        g_off[l][j] = o;
        g_wgt[l][j] = w;
        g_ob [l][j] = (b0 + bi) * (CCH * POOLP) + pos;
    }
}

// -- hot kernel: (channel-group of 8, level, chunk) per block --------------
__global__ __launch_bounds__(256) void k2(
    const float* __restrict__ p2,
    const float* __restrict__ p3,
    const float* __restrict__ p4,
    const float* __restrict__ p5,
    float* __restrict__ out)
{
    const int cg    = blockIdx.x;   // 0..NCG-1
    const int l     = blockIdx.y;   // 0..3
    const int chunk = blockIdx.z;   // 0..CHUNKS-1
    const int ns = g_count[l] * POOLP;

    const int j0 = chunk * 256 + threadIdx.x;
    if (j0 >= ns) return;

    const float* fm;
    int H;
    if      (l == 0) { fm = p2; H = 256; }
    else if (l == 1) { fm = p3; H = 128; }
    else if (l == 2) { fm = p4; H = 64;  }
    else             { fm = p5; H = 32;  }
    const int HW = H * H;

    const int c0 = cg * CPT;
    const float* __restrict__ base = fm + (size_t)c0 * HW;

    const int4*   __restrict__ off = g_off[l];
    const float4* __restrict__ wgt = g_wgt[l];
    const int*    __restrict__ obp = g_ob[l];

    for (int j = j0; j < ns; j += 256 * CHUNKS) {
        const int4   o = __ldg(off + j);
        const float4 w = __ldg(wgt + j);
        const int   ob = __ldg(obp + j);

        float v[CPT];
        #pragma unroll
        for (int k = 0; k < CPT; ++k) {
            const float* __restrict__ pl = base + (size_t)k * HW;
            v[k] = w.x * __ldg(pl + o.x) + w.y * __ldg(pl + o.y)
                 + w.z * __ldg(pl + o.z) + w.w * __ldg(pl + o.w);
        }
        #pragma unroll
        for (int k = 0; k < CPT; ++k)
            out[ob + (c0 + k) * POOLP] = v[k];
    }
}

extern "C" void kernel_launch(void* const* d_in, const int* in_sizes, int n_in,
                              void* d_out, int out_size)
{
    const float* boxes = (const float*)d_in[0];
    const float* p2    = (const float*)d_in[1];
    const float* p3    = (const float*)d_in[2];
    const float* p4    = (const float*)d_in[3];
    const float* p5    = (const float*)d_in[4];
    float* out = (float*)d_out;

    kZ<<<1, 32>>>();
    kAB<<<NBOX / BOXPB, 256>>>(boxes);
    k2<<<dim3(NCG, 4, CHUNKS), 256>>>(p2, p3, p4, p5, out);
}

// round 15
// speedup vs baseline: 1.4403x; 1.4403x over previous
#include <cuda_runtime.h>
#include <cuda_bf16.h>

// ROI-Align (Mask R-CNN multi-level crop_and_resize), POOL=7, C=256, N=1000.
// R10: single mixed-level param array (level packed in high bits of the output
// base) -> no atomics, no compaction, ONE prep launch. Hot kernel keeps the
// proven R8 shape: CPT=4 channels/thread, params loaded once per 4 channels,
// 16 independent gathers per param load.

#define NBOX  1000
#define POOLP 49
#define CCH   256
#define MAXS  (NBOX * POOLP)     // 49000
#define CPT   4                  // channels per thread in hot kernel
#define NCG   (CCH / CPT)        // 64 channel groups
#define CHUNKS 16                // k2 grid.y; stride = 256*CHUNKS = 4096

__device__ int4   g_off[MAXS];   // 4 clamped in-plane offsets
__device__ float4 g_wgt[MAXS];   // 4 bilinear weights (mask folded in)
__device__ int    g_obl[MAXS];   // (level<<28) | (n*12544 + pos)

// -- one-shot prep: per-sample level + bilinear params (no atomics) --------
__global__ __launch_bounds__(256) void kP(const float* __restrict__ boxes) {
    const int s = blockIdx.x * blockDim.x + threadIdx.x;
    if (s >= MAXS) return;

    const int n   = s / POOLP;
    const int pos = s - n * POOLP;
    const int py = pos / 7;
    const int px = pos - py * 7;

    const float y1 = __ldg(boxes + n * 4 + 0);
    const float x1 = __ldg(boxes + n * 4 + 1);
    const float y2 = __ldg(boxes + n * 4 + 2);
    const float x2 = __ldg(boxes + n * 4 + 3);

    // roi_level = clip(round(4 + log2(sqrt(h*w)/0.21875)), 2, 5); round half-to-even.
    const float lvl_f = 4.0f + log2f(sqrtf((y2 - y1) * (x2 - x1)) / 0.21875f);
    int lvl = (int)rintf(lvl_f);
    lvl = lvl < 2 ? 2 : (lvl > 5 ? 5 : lvl);
    const int l = lvl - 2;

    const int H = 256 >> l;
    const int W = H;

    // Match jax f32 arithmetic (t = i / 6.0f as division).
    const float ty = (float)py / 6.0f;
    const float tx = (float)px / 6.0f;
    const float yy = (y1 + (y2 - y1) * ty) * (float)(H - 1);
    const float xx = (x1 + (x2 - x1) * tx) * (float)(W - 1);

    const float y0f = floorf(yy);
    const float x0f = floorf(xx);
    const float wy = yy - y0f;
    const float wx = xx - x0f;

    int iy0 = (int)y0f; iy0 = iy0 < 0 ? 0 : (iy0 > H - 1 ? H - 1 : iy0);
    int iy1 = (iy0 + 1 > H - 1) ? (H - 1) : (iy0 + 1);
    int ix0 = (int)x0f; ix0 = ix0 < 0 ? 0 : (ix0 > W - 1 ? W - 1 : ix0);
    int ix1 = (ix0 + 1 > W - 1) ? (W - 1) : (ix0 + 1);

    const bool inb = (yy >= 0.0f) && (yy <= (float)(H - 1)) &&
                     (xx >= 0.0f) && (xx <= (float)(W - 1));
    const float m = inb ? 1.0f : 0.0f;

    int4 o;
    o.x = iy0 * W + ix0;
    o.y = iy0 * W + ix1;
    o.z = iy1 * W + ix0;
    o.w = iy1 * W + ix1;
    float4 w;
    w.x = m * (1.0f - wy) * (1.0f - wx);
    w.y = m * (1.0f - wy) * wx;
    w.z = m * wy * (1.0f - wx);
    w.w = m * wy * wx;

    g_off[s] = o;
    g_wgt[s] = w;
    g_obl[s] = (l << 28) | (n * (CCH * POOLP) + pos);
}

// -- hot kernel: (channel-group of 4, chunk); mixed levels per block -------
__global__ __launch_bounds__(256) void k2(
    const float* __restrict__ p2,
    const float* __restrict__ p3,
    const float* __restrict__ p4,
    const float* __restrict__ p5,
    float* __restrict__ out)
{
    const int cg    = blockIdx.x;   // 0..NCG-1
    const int chunk = blockIdx.y;   // 0..CHUNKS-1
    const int c0 = cg * CPT;

    const int j0 = chunk * 256 + threadIdx.x;

    for (int j = j0; j < MAXS; j += 256 * CHUNKS) {
        const int4   o   = __ldg(g_off + j);
        const float4 w   = __ldg(g_wgt + j);
        const int    obl = __ldg(g_obl + j);

        const int l  = obl >> 28;
        const int ob = obl & 0x0FFFFFFF;
        const int HW = 65536 >> (l + l);

        const float* fm = (l == 0) ? p2 : (l == 1) ? p3 : (l == 2) ? p4 : p5;
        const float* __restrict__ base = fm + (size_t)c0 * HW;

        float v[CPT];
        #pragma unroll
        for (int k = 0; k < CPT; ++k) {
            const float* __restrict__ pl = base + (size_t)k * HW;
            v[k] = w.x * __ldg(pl + o.x) + w.y * __ldg(pl + o.y)
                 + w.z * __ldg(pl + o.z) + w.w * __ldg(pl + o.w);
        }
        #pragma unroll
        for (int k = 0; k < CPT; ++k)
            out[ob + (c0 + k) * POOLP] = v[k];
    }
}

extern "C" void kernel_launch(void* const* d_in, const int* in_sizes, int n_in,
                              void* d_out, int out_size)
{
    const float* boxes = (const float*)d_in[0];
    const float* p2    = (const float*)d_in[1];
    const float* p3    = (const float*)d_in[2];
    const float* p4    = (const float*)d_in[3];
    const float* p5    = (const float*)d_in[4];
    float* out = (float*)d_out;

    kP<<<(MAXS + 255) / 256, 256>>>(boxes);
    k2<<<dim3(NCG, CHUNKS), 256>>>(p2, p3, p4, p5, out);
}